// round 6
// baseline (speedup 1.0000x reference)
#include <cuda_runtime.h>
#include <cstdint>

// Problem shape (fixed by the dataset)
#define B_BATCH 4
#define E_EDGES 320000
#define N_NODES 10000
#define F_FEAT  64

// out is [B, N, F] f32 = 2,560,000 floats = 640,000 float4
__global__ void zero_out_kernel(float4* __restrict__ out, int n4) {
    int i = blockIdx.x * blockDim.x + threadIdx.x;
    if (i < n4) out[i] = make_float4(0.f, 0.f, 0.f, 0.f);
}

// 16 threads per edge: each thread handles one float4 (4 features) of the
// 64-feature message vector. Reads are perfectly coalesced (consecutive
// threads -> consecutive float4). Scatter uses no-return vectorized
// reduction (red.global.add.v4.f32) so there is no load round-trip and
// 4x fewer L2 atomic ops than scalar atomicAdd.
__global__ __launch_bounds__(256) void scatter_add_kernel(
    const float4* __restrict__ msg,      // [B, E, 16] float4
    const int*    __restrict__ start_idx,// [B, E]
    float*        __restrict__ out)      // [B, N, 64]
{
    const int b = blockIdx.y;
    const int t = blockIdx.x * blockDim.x + threadIdx.x;  // 0 .. E*16-1
    const int e  = t >> 4;       // edge within batch
    const int f4 = t & 15;       // which float4 of the feature vector
    if (e >= E_EDGES) return;

    const long long edge = (long long)b * E_EDGES + e;
    const float4 v = msg[edge * 16 + f4];

    const int node = start_idx[edge];   // 16 lanes broadcast-read same word

    float* dst = out + ((long long)b * N_NODES + node) * F_FEAT + f4 * 4;
    asm volatile(
        "red.global.add.v4.f32 [%0], {%1, %2, %3, %4};"
        :: "l"(dst), "f"(v.x), "f"(v.y), "f"(v.z), "f"(v.w)
        : "memory");
}

extern "C" void kernel_launch(void* const* d_in, const int* in_sizes, int n_in,
                              void* d_out, int out_size) {
    const float4* msg = (const float4*)d_in[0];       // msg_vectors [B,E,F] f32
    const int*    idx = (const int*)d_in[1];          // start_indices [B,E] i32
    // d_in[2] = h_v, unused by the reference computation
    float* out = (float*)d_out;                       // [B,N,F] f32

    // 1) zero the output (harness poisons it with 0xAA)
    const int n4 = (B_BATCH * N_NODES * F_FEAT) / 4;  // 640,000
    zero_out_kernel<<<(n4 + 255) / 256, 256>>>((float4*)out, n4);

    // 2) scatter-add: E*16 threads per batch, batch on grid.y
    const int threads_per_batch = E_EDGES * 16;       // 5,120,000
    dim3 grid((threads_per_batch + 255) / 256, B_BATCH);
    scatter_add_kernel<<<grid, 256>>>(msg, idx, out);
}

// round 7
// speedup vs baseline: 1.0478x; 1.0478x over previous
#include <cuda_runtime.h>
#include <cstdint>

// Problem shape (fixed by the dataset)
#define B_BATCH 4
#define E_EDGES 320000
#define N_NODES 10000
#define F_FEAT  64

// out is [B, N, F] f32 = 2,560,000 floats = 640,000 float4.
// Each thread writes 4 float4 (64B) to cut CTA count and launch overhead.
__global__ __launch_bounds__(256) void zero_out_kernel(float4* __restrict__ out, int n4) {
    int i = (blockIdx.x * blockDim.x + threadIdx.x) * 4;
    if (i + 3 < n4) {
        const float4 z = make_float4(0.f, 0.f, 0.f, 0.f);
        out[i + 0] = z;
        out[i + 1] = z;
        out[i + 2] = z;
        out[i + 3] = z;
    } else {
        for (int k = i; k < n4; ++k) out[k] = make_float4(0.f, 0.f, 0.f, 0.f);
    }
}

// 16 threads cover the 64-feature vector of an edge (one float4 each).
// Each thread processes 4 CONSECUTIVE edges: all 8 loads (4 idx + 4 msg.128)
// are issued up front (MLP_p1 ~ 8) before the 4 no-return vectorized
// reductions. This hides DRAM latency that the 1-edge-per-thread version
// left exposed (DRAM was only 58.5% of peak).
__global__ __launch_bounds__(256) void scatter_add_kernel(
    const float4* __restrict__ msg,       // [B, E, 16] float4
    const int*    __restrict__ start_idx, // [B, E]
    float*        __restrict__ out)       // [B, N, 64]
{
    const int b  = blockIdx.y;
    const int t  = blockIdx.x * blockDim.x + threadIdx.x;
    const int f4 = t & 15;          // which float4 of the feature vector
    const int e0 = (t >> 4) * 4;    // first of 4 edges handled by this thread
    if (e0 >= E_EDGES) return;

    const long long base = (long long)b * E_EDGES;

    // Front-batched loads: 4 index words (lanes 0-15 broadcast) and
    // 4x LDG.128 of msg. Within a warp each msg load covers two contiguous
    // 256B segments (lanes 0-15 edge g, lanes 16-31 edge g+4) - fully coalesced.
    int    node[4];
    float4 v[4];
#pragma unroll
    for (int u = 0; u < 4; ++u) {
        const long long e = base + e0 + u;
        node[u] = __ldg(start_idx + e);
        v[u]    = __ldg(msg + e * 16 + f4);
    }

#pragma unroll
    for (int u = 0; u < 4; ++u) {
        float* dst = out + ((long long)b * N_NODES + node[u]) * F_FEAT + f4 * 4;
        asm volatile(
            "red.global.add.v4.f32 [%0], {%1, %2, %3, %4};"
            :: "l"(dst), "f"(v[u].x), "f"(v[u].y), "f"(v[u].z), "f"(v[u].w)
            : "memory");
    }
}

extern "C" void kernel_launch(void* const* d_in, const int* in_sizes, int n_in,
                              void* d_out, int out_size) {
    const float4* msg = (const float4*)d_in[0];   // msg_vectors [B,E,F] f32
    const int*    idx = (const int*)d_in[1];      // start_indices [B,E] i32
    // d_in[2] = h_v, unused by the reference computation
    float* out = (float*)d_out;                   // [B,N,F] f32

    // 1) zero the output (harness poisons it with 0xAA)
    const int n4 = (B_BATCH * N_NODES * F_FEAT) / 4;        // 640,000
    const int zthreads = (n4 + 3) / 4;                      // 160,000
    zero_out_kernel<<<(zthreads + 255) / 256, 256>>>((float4*)out, n4);

    // 2) scatter-add: E*16/4 threads per batch, batch on grid.y
    const int threads_per_batch = E_EDGES * 16 / 4;         // 1,280,000
    dim3 grid(threads_per_batch / 256, B_BATCH);            // (5000, 4)
    scatter_add_kernel<<<grid, 256>>>(msg, idx, out);
}